// round 1
// baseline (speedup 1.0000x reference)
#include <cuda_runtime.h>

#define D     256
#define D4    (D/4)
#define KCB   1024
#define BM    128
#define BN    128
#define BK    8

// ---------------- device scratch (no allocations allowed) ----------------
__device__ float  g_e2[KCB];
__device__ double g_loss_sum;

// ---------------- prep: e2[k] = sum(emb[k]^2), zero loss/usages ----------
__global__ void vq_prep(const float* __restrict__ emb,
                        float* __restrict__ loss_usages /* [1+KCB] */) {
    int gtid = blockIdx.x * blockDim.x + threadIdx.x;
    int w    = gtid >> 5;
    int lane = threadIdx.x & 31;
    if (w < KCB) {
        const float4* e = (const float4*)(emb + (size_t)w * D);
        float s = 0.f;
        float4 v0 = e[lane];
        float4 v1 = e[lane + 32];
        s = fmaf(v0.x, v0.x, s); s = fmaf(v0.y, v0.y, s);
        s = fmaf(v0.z, v0.z, s); s = fmaf(v0.w, v0.w, s);
        s = fmaf(v1.x, v1.x, s); s = fmaf(v1.y, v1.y, s);
        s = fmaf(v1.z, v1.z, s); s = fmaf(v1.w, v1.w, s);
        #pragma unroll
        for (int o = 16; o > 0; o >>= 1)
            s += __shfl_xor_sync(0xffffffffu, s, o);
        if (lane == 0) g_e2[w] = s;
    }
    if (gtid < 1 + KCB) loss_usages[gtid] = 0.f;
    if (gtid == 0)      g_loss_sum = 0.0;
}

// ---------------- main: fused GEMM + argmin + gather + loss + hist -------
__global__ __launch_bounds__(256, 2)
void vq_main(const float* __restrict__ x,
             const float* __restrict__ emb,
             float* __restrict__ out_values,
             float* __restrict__ out_indexes,
             float* __restrict__ out_usages) {
    __shared__ float As[BK][BM];
    __shared__ float Bs[BK][BN];
    __shared__ float sx2[BM];
    __shared__ float redv[BM][16];
    __shared__ int   redk[BM][16];
    __shared__ int   fidx[BM];
    __shared__ float lred[256];

    const int    tid = threadIdx.x;
    const int    tx  = tid & 15;
    const int    ty  = tid >> 4;
    const size_t m0  = (size_t)blockIdx.x * BM;

    // ---- per-row ||x||^2 ----
    if (tid < BM) {
        const float4* xr = (const float4*)(x + (m0 + tid) * D);
        float s0 = 0.f, s1 = 0.f, s2 = 0.f, s3 = 0.f;
        #pragma unroll
        for (int i = 0; i < D4; i += 4) {
            float4 v0 = xr[i + 0];
            float4 v1 = xr[i + 1];
            float4 v2 = xr[i + 2];
            float4 v3 = xr[i + 3];
            s0 = fmaf(v0.x, v0.x, s0); s0 = fmaf(v0.y, v0.y, s0);
            s0 = fmaf(v0.z, v0.z, s0); s0 = fmaf(v0.w, v0.w, s0);
            s1 = fmaf(v1.x, v1.x, s1); s1 = fmaf(v1.y, v1.y, s1);
            s1 = fmaf(v1.z, v1.z, s1); s1 = fmaf(v1.w, v1.w, s1);
            s2 = fmaf(v2.x, v2.x, s2); s2 = fmaf(v2.y, v2.y, s2);
            s2 = fmaf(v2.z, v2.z, s2); s2 = fmaf(v2.w, v2.w, s2);
            s3 = fmaf(v3.x, v3.x, s3); s3 = fmaf(v3.y, v3.y, s3);
            s3 = fmaf(v3.z, v3.z, s3); s3 = fmaf(v3.w, v3.w, s3);
        }
        sx2[tid] = (s0 + s1) + (s2 + s3);
    }

    float bestv[8];
    int   bestk[8];
    #pragma unroll
    for (int i = 0; i < 8; i++) { bestv[i] = __int_as_float(0x7f800000); bestk[i] = 0; }

    const int arow  = tid >> 1;        // 0..127
    const int acol4 = (tid & 1) * 4;   // 0 or 4 within the 8-wide k-chunk

    for (int n0 = 0; n0 < KCB; n0 += BN) {
        float acc[8][8];
        #pragma unroll
        for (int i = 0; i < 8; i++)
            #pragma unroll
            for (int j = 0; j < 8; j++) acc[i][j] = 0.f;

        for (int k0 = 0; k0 < D; k0 += BK) {
            __syncthreads();
            // load A tile (x rows), transposed into k-major smem
            float4 av = *(const float4*)(x + (m0 + arow) * D + k0 + acol4);
            As[acol4 + 0][arow] = av.x;
            As[acol4 + 1][arow] = av.y;
            As[acol4 + 2][arow] = av.z;
            As[acol4 + 3][arow] = av.w;
            // load B tile (codewords)
            float4 bv = *(const float4*)(emb + (size_t)(n0 + arow) * D + k0 + acol4);
            Bs[acol4 + 0][arow] = bv.x;
            Bs[acol4 + 1][arow] = bv.y;
            Bs[acol4 + 2][arow] = bv.z;
            Bs[acol4 + 3][arow] = bv.w;
            __syncthreads();

            #pragma unroll
            for (int k = 0; k < BK; k++) {
                float4 a0 = *(const float4*)&As[k][ty * 8];
                float4 a1 = *(const float4*)&As[k][ty * 8 + 4];
                float4 b0 = *(const float4*)&Bs[k][tx * 8];
                float4 b1 = *(const float4*)&Bs[k][tx * 8 + 4];
                float a[8] = {a0.x, a0.y, a0.z, a0.w, a1.x, a1.y, a1.z, a1.w};
                float b[8] = {b0.x, b0.y, b0.z, b0.w, b1.x, b1.y, b1.z, b1.w};
                #pragma unroll
                for (int i = 0; i < 8; i++)
                    #pragma unroll
                    for (int j = 0; j < 8; j++)
                        acc[i][j] = fmaf(a[i], b[j], acc[i][j]);
            }
        }

        // argmin update: dist = (x2 + e2) - 2*dot   (reference rounding order)
        #pragma unroll
        for (int j = 0; j < 8; j++) {
            int   kk = n0 + tx * 8 + j;
            float ek = g_e2[kk];
            #pragma unroll
            for (int i = 0; i < 8; i++) {
                float dist = fmaf(-2.0f, acc[i][j], sx2[ty * 8 + i] + ek);
                if (dist < bestv[i]) { bestv[i] = dist; bestk[i] = kk; }
            }
        }
    }

    // ---- cross-thread argmin reduce (tie -> min index = first occurrence) ----
    #pragma unroll
    for (int i = 0; i < 8; i++) {
        redv[ty * 8 + i][tx] = bestv[i];
        redk[ty * 8 + i][tx] = bestk[i];
    }
    __syncthreads();

    if (tid < BM) {
        float bv = redv[tid][0];
        int   bk = redk[tid][0];
        #pragma unroll
        for (int t = 1; t < 16; t++) {
            float v = redv[tid][t];
            int   k = redk[tid][t];
            if (v < bv || (v == bv && k < bk)) { bv = v; bk = k; }
        }
        fidx[tid] = bk;
        out_indexes[m0 + tid] = (float)bk;
        atomicAdd(&out_usages[bk], 1.0f);
    }
    __syncthreads();

    // ---- gather values, write values_st = x + (values - x), loss partial ----
    float lp = 0.f;
    const float4* x4 = (const float4*)x;
    float4*       o4 = (float4*)out_values;
    #pragma unroll 4
    for (int c = tid; c < BM * D4; c += 256) {
        int    row = c >> 6;
        int    q   = c & 63;
        size_t g   = (m0 + row) * (size_t)D4 + q;
        float4 xv  = x4[g];
        float4 ev  = ((const float4*)(emb + (size_t)fidx[row] * D))[q];
        float4 st, df;
        st.x = xv.x + (ev.x - xv.x);  df.x = xv.x - ev.x;
        st.y = xv.y + (ev.y - xv.y);  df.y = xv.y - ev.y;
        st.z = xv.z + (ev.z - xv.z);  df.z = xv.z - ev.z;
        st.w = xv.w + (ev.w - xv.w);  df.w = xv.w - ev.w;
        lp = fmaf(df.x, df.x, lp); lp = fmaf(df.y, df.y, lp);
        lp = fmaf(df.z, df.z, lp); lp = fmaf(df.w, df.w, lp);
        o4[g] = st;
    }
    lred[tid] = lp;
    __syncthreads();
    #pragma unroll
    for (int s = 128; s > 0; s >>= 1) {
        if (tid < s) lred[tid] += lred[tid + s];
        __syncthreads();
    }
    if (tid == 0) atomicAdd(&g_loss_sum, (double)lred[0]);
}

// ---------------- finalize: loss = l + l*BETA ----------------------------
__global__ void vq_finalize(float* __restrict__ out_loss, long long count) {
    double m = g_loss_sum / (double)count;
    float  l = (float)m;             // loss1 == loss2 numerically
    out_loss[0] = l + l * 0.2f;      // loss1 + loss2 * BETA
}

// ---------------- entry ---------------------------------------------------
extern "C" void kernel_launch(void* const* d_in, const int* in_sizes, int n_in,
                              void* d_out, int out_size) {
    const float* x   = (const float*)d_in[0];
    const float* emb = (const float*)d_in[1];
    const int M = in_sizes[0] / D;          // 131072

    float* out         = (float*)d_out;
    float* out_values  = out;                               // M*D
    float* out_indexes = out + (size_t)M * D;               // M
    float* out_loss    = out_indexes + M;                   // 1
    float* out_usages  = out_loss + 1;                      // KCB

    // prep: 1024 warps for e2 + zero [loss|usages]
    vq_prep<<<(KCB * 32 + 255) / 256, 256>>>(emb, out_loss);

    // main fused kernel
    vq_main<<<M / BM, 256>>>(x, emb, out_values, out_indexes, out_usages);

    // loss scalar
    vq_finalize<<<1, 1>>>(out_loss, (long long)M * D);
}

// round 2
// speedup vs baseline: 1.0785x; 1.0785x over previous
#include <cuda_runtime.h>
#include <cuda_bf16.h>
#include <cstdint>

#define D     256
#define D4    (D/4)
#define KCB   1024
#define BM    128
#define STR   264            // bf16 elems per smem row (256 + 8 pad) -> 528B
#define CMAX  32

// ---- dynamic smem layout (bytes) ----
#define OFF_XS    0                       // 128*264*2 = 67584
#define OFF_ES    67584                   // 2 bufs * 67584 = 135168
#define OFF_SE2   202752                  // 1024 f32 = 4096
#define OFF_SX2   206848                  // 128 f32
#define OFF_SMG   207360                  // 128 f32
#define OFF_RMIN  207872                  // 128 u32
#define OFF_CNT   208384                  // 128 u32
#define OFF_CAND  208896                  // 128*32*2 = 8192
#define OFF_FIDX  217088                  // 128 i32
#define OFF_LRED  217600                  // 256 f32
#define SMEM_TOTAL 218624

// ---------------- device scratch ----------------
__device__ float          g_e2[KCB];
__device__ __nv_bfloat16  g_eb[KCB * D];
__device__ double         g_loss_sum;

// ---------------- prep: e2 (exact, round-1 order), emb->bf16, zero outs ----
__global__ void vq_prep(const float* __restrict__ emb,
                        float* __restrict__ loss_usages /* [1+KCB] */) {
    int gtid = blockIdx.x * blockDim.x + threadIdx.x;
    int w    = gtid >> 5;
    int lane = threadIdx.x & 31;
    if (w < KCB) {
        const float4* e = (const float4*)(emb + (size_t)w * D);
        float s = 0.f;
        float4 v0 = e[lane];
        float4 v1 = e[lane + 32];
        s = fmaf(v0.x, v0.x, s); s = fmaf(v0.y, v0.y, s);
        s = fmaf(v0.z, v0.z, s); s = fmaf(v0.w, v0.w, s);
        s = fmaf(v1.x, v1.x, s); s = fmaf(v1.y, v1.y, s);
        s = fmaf(v1.z, v1.z, s); s = fmaf(v1.w, v1.w, s);
        #pragma unroll
        for (int o = 16; o > 0; o >>= 1)
            s += __shfl_xor_sync(0xffffffffu, s, o);
        if (lane == 0) g_e2[w] = s;
        // bf16 conversion of this codeword
        __nv_bfloat16* dst = g_eb + (size_t)w * D;
        dst[4*lane + 0] = __float2bfloat16_rn(v0.x);
        dst[4*lane + 1] = __float2bfloat16_rn(v0.y);
        dst[4*lane + 2] = __float2bfloat16_rn(v0.z);
        dst[4*lane + 3] = __float2bfloat16_rn(v0.w);
        dst[128 + 4*lane + 0] = __float2bfloat16_rn(v1.x);
        dst[128 + 4*lane + 1] = __float2bfloat16_rn(v1.y);
        dst[128 + 4*lane + 2] = __float2bfloat16_rn(v1.z);
        dst[128 + 4*lane + 3] = __float2bfloat16_rn(v1.w);
    }
    if (gtid < 1 + KCB) loss_usages[gtid] = 0.f;
    if (gtid == 0)      g_loss_sum = 0.0;
}

// ---------------- asm helpers ----------------
__device__ __forceinline__ uint32_t s2u(const void* p) {
    return (uint32_t)__cvta_generic_to_shared(p);
}
__device__ __forceinline__ void ldsm4(uint32_t& r0, uint32_t& r1,
                                      uint32_t& r2, uint32_t& r3, uint32_t a) {
    asm volatile("ldmatrix.sync.aligned.m8n8.x4.shared.b16 {%0,%1,%2,%3}, [%4];"
                 : "=r"(r0), "=r"(r1), "=r"(r2), "=r"(r3) : "r"(a));
}
__device__ __forceinline__ void mma16816(float* c, const uint32_t* a, const uint32_t* b) {
    asm volatile(
        "mma.sync.aligned.m16n8k16.row.col.f32.bf16.bf16.f32 "
        "{%0,%1,%2,%3},{%4,%5,%6,%7},{%8,%9},{%0,%1,%2,%3};"
        : "+f"(c[0]), "+f"(c[1]), "+f"(c[2]), "+f"(c[3])
        : "r"(a[0]), "r"(a[1]), "r"(a[2]), "r"(a[3]), "r"(b[0]), "r"(b[1]));
}
__device__ __forceinline__ void cpasync16(uint32_t dst, const void* src) {
    asm volatile("cp.async.cg.shared.global [%0], [%1], 16;" :: "r"(dst), "l"(src));
}

// ---------------- main fused kernel ----------------
__global__ __launch_bounds__(256, 1)
void vq_main(const float* __restrict__ x,
             const float* __restrict__ emb,
             float* __restrict__ out_values,
             float* __restrict__ out_indexes,
             float* __restrict__ out_usages) {
    extern __shared__ __align__(16) char smem[];
    __nv_bfloat16* xs    = (__nv_bfloat16*)(smem + OFF_XS);
    float*    se2        = (float*)(smem + OFF_SE2);
    float*    sx2        = (float*)(smem + OFF_SX2);
    float*    smg        = (float*)(smem + OFF_SMG);
    uint32_t* rowminU    = (uint32_t*)(smem + OFF_RMIN);
    uint32_t* scnt       = (uint32_t*)(smem + OFF_CNT);
    uint16_t* scand      = (uint16_t*)(smem + OFF_CAND);
    int*      fidx       = (int*)(smem + OFF_FIDX);
    float*    lred       = (float*)(smem + OFF_LRED);

    const int    tid  = threadIdx.x;
    const int    warp = tid >> 5;
    const int    lane = tid & 31;
    const int    wm   = warp >> 1;       // 0..3
    const int    wn   = warp & 1;        // 0..1
    const size_t m0   = (size_t)blockIdx.x * BM;

    // ---- issue chunk0 of codebook (bf16) via cp.async ----
    {
        __nv_bfloat16* es0 = (__nv_bfloat16*)(smem + OFF_ES);
        #pragma unroll
        for (int i = 0; i < 16; i++) {
            int lin = tid + i * 256;
            int r   = lin >> 5, seg = lin & 31;
            cpasync16(s2u(es0 + r * STR + seg * 8), g_eb + (size_t)r * D + seg * 8);
        }
        asm volatile("cp.async.commit_group;");
    }

    // ---- load x tile -> bf16 smem ----
    {
        #pragma unroll
        for (int i = 0; i < 32; i++) {
            int lin = tid + i * 256;
            int r = lin >> 6, c4 = lin & 63;
            float4 v = *(const float4*)(x + (m0 + r) * D + c4 * 4);
            __nv_bfloat162 p0 = __nv_bfloat162(__float2bfloat16_rn(v.x), __float2bfloat16_rn(v.y));
            __nv_bfloat162 p1 = __nv_bfloat162(__float2bfloat16_rn(v.z), __float2bfloat16_rn(v.w));
            *(__nv_bfloat162*)(xs + r * STR + c4 * 4)     = p0;
            *(__nv_bfloat162*)(xs + r * STR + c4 * 4 + 2) = p1;
        }
    }

    // ---- per-row x2 (exact, round-1 order) + Sum|x| -> margin ----
    if (tid < BM) {
        const float4* xr = (const float4*)(x + (m0 + tid) * D);
        float s0 = 0.f, s1 = 0.f, s2 = 0.f, s3 = 0.f, sa = 0.f;
        #pragma unroll
        for (int i = 0; i < D4; i += 4) {
            float4 v0 = xr[i + 0];
            float4 v1 = xr[i + 1];
            float4 v2 = xr[i + 2];
            float4 v3 = xr[i + 3];
            s0 = fmaf(v0.x, v0.x, s0); s0 = fmaf(v0.y, v0.y, s0);
            s0 = fmaf(v0.z, v0.z, s0); s0 = fmaf(v0.w, v0.w, s0);
            s1 = fmaf(v1.x, v1.x, s1); s1 = fmaf(v1.y, v1.y, s1);
            s1 = fmaf(v1.z, v1.z, s1); s1 = fmaf(v1.w, v1.w, s1);
            s2 = fmaf(v2.x, v2.x, s2); s2 = fmaf(v2.y, v2.y, s2);
            s2 = fmaf(v2.z, v2.z, s2); s2 = fmaf(v2.w, v2.w, s2);
            s3 = fmaf(v3.x, v3.x, s3); s3 = fmaf(v3.y, v3.y, s3);
            s3 = fmaf(v3.z, v3.z, s3); s3 = fmaf(v3.w, v3.w, s3);
            sa += fabsf(v0.x) + fabsf(v0.y) + fabsf(v0.z) + fabsf(v0.w)
                + fabsf(v1.x) + fabsf(v1.y) + fabsf(v1.z) + fabsf(v1.w)
                + fabsf(v2.x) + fabsf(v2.y) + fabsf(v2.z) + fabsf(v2.w)
                + fabsf(v3.x) + fabsf(v3.y) + fabsf(v3.z) + fabsf(v3.w);
        }
        sx2[tid] = (s0 + s1) + (s2 + s3);
        smg[tid] = 0.0084f * sa + 0.2f;        // >= 2*bf16 error bound + slack
        rowminU[tid] = __float_as_uint(3.0e38f);
        scnt[tid]    = 0u;
    }
    // e2 table to smem
    {
        float4 v = *((const float4*)g_e2 + tid);
        *((float4*)se2 + tid) = v;
    }

    // ---- per-thread row caches ----
    const int ln4 = lane >> 2, lq = lane & 3;
    int   rowc[4];
    float x2c[4], mgc[4];
    #pragma unroll
    for (int mi = 0; mi < 2; mi++)
        #pragma unroll
        for (int h = 0; h < 2; h++) {
            int r = wm * 32 + mi * 16 + h * 8 + ln4;
            rowc[mi * 2 + h] = r;
        }

    // ==== chunk loop: 8 x 128 codewords ====
    for (int c = 0; c < 8; c++) {
        if (c + 1 < 8) {
            __nv_bfloat16* esn = (__nv_bfloat16*)(smem + OFF_ES + ((c + 1) & 1) * 67584);
            const __nv_bfloat16* src = g_eb + (size_t)(c + 1) * 128 * D;
            #pragma unroll
            for (int i = 0; i < 16; i++) {
                int lin = tid + i * 256;
                int r   = lin >> 5, seg = lin & 31;
                cpasync16(s2u(esn + r * STR + seg * 8), src + (size_t)r * D + seg * 8);
            }
            asm volatile("cp.async.commit_group;");
            asm volatile("cp.async.wait_group 1;");
        } else {
            asm volatile("cp.async.wait_group 0;");
        }
        __syncthreads();
        if (c == 0) {   // row caches need sx2/smg ready (first sync just happened)
            #pragma unroll
            for (int q = 0; q < 4; q++) { x2c[q] = sx2[rowc[q]]; mgc[q] = smg[rowc[q]]; }
        }

        __nv_bfloat16* esb = (__nv_bfloat16*)(smem + OFF_ES + (c & 1) * 67584);

        float acc[2][8][4];
        #pragma unroll
        for (int mi = 0; mi < 2; mi++)
            #pragma unroll
            for (int ni = 0; ni < 8; ni++)
                #pragma unroll
                for (int v = 0; v < 4; v++) acc[mi][ni][v] = 0.f;

        #pragma unroll 2
        for (int ks = 0; ks < 16; ks++) {
            const int k0 = ks * 16;
            uint32_t a[2][4];
            #pragma unroll
            for (int mi = 0; mi < 2; mi++) {
                int r   = wm * 32 + mi * 16 + (lane & 15);
                int col = k0 + ((lane >> 4) << 3);
                ldsm4(a[mi][0], a[mi][1], a[mi][2], a[mi][3], s2u(xs + r * STR + col));
            }
            uint32_t b[8][2];
            #pragma unroll
            for (int nt = 0; nt < 4; nt++) {
                int nr  = wn * 64 + nt * 16 + (lane & 7) + (((lane >> 4) & 1) << 3);
                int col = k0 + (((lane >> 3) & 1) << 3);
                uint32_t r0, r1, r2, r3;
                ldsm4(r0, r1, r2, r3, s2u(esb + nr * STR + col));
                b[nt * 2][0] = r0;  b[nt * 2][1] = r1;
                b[nt * 2 + 1][0] = r2;  b[nt * 2 + 1][1] = r3;
            }
            #pragma unroll
            for (int mi = 0; mi < 2; mi++)
                #pragma unroll
                for (int ni = 0; ni < 8; ni++)
                    mma16816(acc[mi][ni], a[mi], b[ni]);
        }

        // ---- chunk epilogue: approx dist, running min + candidate collect ----
        float se2c[16];
        #pragma unroll
        for (int ni = 0; ni < 8; ni++) {
            se2c[ni * 2]     = se2[c * 128 + wn * 64 + ni * 8 + 2 * lq];
            se2c[ni * 2 + 1] = se2[c * 128 + wn * 64 + ni * 8 + 2 * lq + 1];
        }
        #pragma unroll
        for (int mi = 0; mi < 2; mi++) {
            #pragma unroll
            for (int h = 0; h < 2; h++) {
                const int   row = rowc[mi * 2 + h];
                const float x2  = x2c[mi * 2 + h];
                const float mg  = mgc[mi * 2 + h];
                float rm = __uint_as_float(rowminU[row]);   // stale OK (superset)
                #pragma unroll
                for (int ni = 0; ni < 8; ni++) {
                    #pragma unroll
                    for (int cc = 0; cc < 2; cc++) {
                        float d  = fmaf(-2.0f, acc[mi][ni][h * 2 + cc],
                                        x2 + se2c[ni * 2 + cc]);
                        float dk = d + 1024.0f;
                        if (dk < rm + mg) {
                            int kg = c * 128 + wn * 64 + ni * 8 + 2 * lq + cc;
                            uint32_t p = atomicAdd(&scnt[row], 1u);
                            if (p < CMAX) scand[row * CMAX + p] = (uint16_t)kg;
                            if (dk < rm) atomicMin(&rowminU[row], __float_as_uint(dk));
                            rm = __uint_as_float(rowminU[row]);
                        }
                    }
                }
            }
        }
        __syncthreads();
    }

    // ==== pass 2: exact fp32 re-check of candidates (round-1 bit order) ====
    // warp w handles rows w*16 .. w*16+15
    for (int i = 0; i < 16; i++) {
        int row = warp * 16 + i;
        uint32_t n = scnt[row];
        float bd = 3.0e38f;
        int   bk = 0x7fffffff;
        if (n <= CMAX) {
            if (lane < (int)n) {
                int k = scand[row * CMAX + lane];
                const float4* xr = (const float4*)(x + (m0 + row) * D);
                const float4* er = (const float4*)(emb + (size_t)k * D);
                float a = 0.f;
                #pragma unroll 8
                for (int kk = 0; kk < D4; kk++) {
                    float4 xv = xr[kk];
                    float4 ev = er[kk];
                    a = fmaf(xv.x, ev.x, a); a = fmaf(xv.y, ev.y, a);
                    a = fmaf(xv.z, ev.z, a); a = fmaf(xv.w, ev.w, a);
                }
                bd = fmaf(-2.0f, a, sx2[row] + se2[k]);
                bk = k;
            }
        } else {
            // rare fallback: full exact scan
            for (int k = lane; k < KCB; k += 32) {
                const float4* xr = (const float4*)(x + (m0 + row) * D);
                const float4* er = (const float4*)(emb + (size_t)k * D);
                float a = 0.f;
                #pragma unroll 8
                for (int kk = 0; kk < D4; kk++) {
                    float4 xv = xr[kk];
                    float4 ev = er[kk];
                    a = fmaf(xv.x, ev.x, a); a = fmaf(xv.y, ev.y, a);
                    a = fmaf(xv.z, ev.z, a); a = fmaf(xv.w, ev.w, a);
                }
                float d = fmaf(-2.0f, a, sx2[row] + se2[k]);
                if (d < bd || (d == bd && k < bk)) { bd = d; bk = k; }
            }
        }
        #pragma unroll
        for (int o = 16; o > 0; o >>= 1) {
            float od = __shfl_xor_sync(0xffffffffu, bd, o);
            int   ok = __shfl_xor_sync(0xffffffffu, bk, o);
            if (od < bd || (od == bd && ok < bk)) { bd = od; bk = ok; }
        }
        if (lane == 0) {
            fidx[row] = bk;
            out_indexes[m0 + row] = (float)bk;
            atomicAdd(&out_usages[bk], 1.0f);
        }
    }
    __syncthreads();

    // ==== pass 3: gather, values_st, loss (round-1 identical) ====
    float lp = 0.f;
    const float4* x4 = (const float4*)x;
    float4*       o4 = (float4*)out_values;
    #pragma unroll 4
    for (int cc = tid; cc < BM * D4; cc += 256) {
        int    row = cc >> 6;
        int    q   = cc & 63;
        size_t g   = (m0 + row) * (size_t)D4 + q;
        float4 xv  = x4[g];
        float4 ev  = ((const float4*)(emb + (size_t)fidx[row] * D))[q];
        float4 st, df;
        st.x = xv.x + (ev.x - xv.x);  df.x = xv.x - ev.x;
        st.y = xv.y + (ev.y - xv.y);  df.y = xv.y - ev.y;
        st.z = xv.z + (ev.z - xv.z);  df.z = xv.z - ev.z;
        st.w = xv.w + (ev.w - xv.w);  df.w = xv.w - ev.w;
        lp = fmaf(df.x, df.x, lp); lp = fmaf(df.y, df.y, lp);
        lp = fmaf(df.z, df.z, lp); lp = fmaf(df.w, df.w, lp);
        o4[g] = st;
    }
    lred[tid] = lp;
    __syncthreads();
    #pragma unroll
    for (int s = 128; s > 0; s >>= 1) {
        if (tid < s) lred[tid] += lred[tid + s];
        __syncthreads();
    }
    if (tid == 0) atomicAdd(&g_loss_sum, (double)lred[0]);
}

// ---------------- finalize ----------------
__global__ void vq_finalize(float* __restrict__ out_loss, long long count) {
    double m = g_loss_sum / (double)count;
    float  l = (float)m;
    out_loss[0] = l + l * 0.2f;
}

// ---------------- entry ----------------
extern "C" void kernel_launch(void* const* d_in, const int* in_sizes, int n_in,
                              void* d_out, int out_size) {
    const float* x   = (const float*)d_in[0];
    const float* emb = (const float*)d_in[1];
    const int M = in_sizes[0] / D;          // 131072

    float* out         = (float*)d_out;
    float* out_values  = out;                               // M*D
    float* out_indexes = out + (size_t)M * D;               // M
    float* out_loss    = out_indexes + M;                   // 1
    float* out_usages  = out_loss + 1;                      // KCB

    cudaFuncSetAttribute(vq_main, cudaFuncAttributeMaxDynamicSharedMemorySize,
                         SMEM_TOTAL);

    vq_prep<<<(KCB * 32 + 255) / 256, 256>>>(emb, out_loss);
    vq_main<<<M / BM, 256, SMEM_TOTAL>>>(x, emb, out_values, out_indexes, out_usages);
    vq_finalize<<<1, 1>>>(out_loss, (long long)M * D);
}